// round 10
// baseline (speedup 1.0000x reference)
#include <cuda_runtime.h>
#include <math.h>
#include <stdint.h>

typedef unsigned long long ull;
typedef unsigned int uint;

// ---------------- scratch (no allocations allowed) ----------------
// g_hc[b][chunk][4096]: per 64-j chunk, tf32 (hi-only) interleaved:
//   float index = kt*512 + c*8 + q*2 + s,  s=0: h[j=8kt+q][c], s=1: h[j=8kt+q+4][c]
__device__ float g_hc[16 * 32 * 4096];    // 8.4 MB
__device__ float g_ssrc[16 * 2048];
__device__ float g_sdst[16 * 2048];

// ---------------- helpers ----------------
__device__ __forceinline__ uint smem_u32(const void* p) {
    uint a;
    asm("{ .reg .u64 t; cvta.to.shared.u64 t, %1; cvt.u32.u64 %0, t; }" : "=r"(a) : "l"(p));
    return a;
}
__device__ __forceinline__ ull pack2(float lo, float hi) {
    ull r; asm("mov.b64 %0, {%1, %2};" : "=l"(r) : "f"(lo), "f"(hi)); return r;
}
__device__ __forceinline__ void unpack2(ull v, float& lo, float& hi) {
    asm("mov.b64 {%0, %1}, %2;" : "=f"(lo), "=f"(hi) : "l"(v));
}
__device__ __forceinline__ ull fma2(ull a, ull b, ull c) {
    ull d; asm("fma.rn.f32x2 %0, %1, %2, %3;" : "=l"(d) : "l"(a), "l"(b), "l"(c)); return d;
}
__device__ __forceinline__ float rna_tf32(float x) {
    float r; asm("cvt.rna.tf32.f32 %0, %1;" : "=f"(r) : "f"(x)); return r;
}
__device__ __forceinline__ void cpasync16(uint dst, const void* src) {
    asm volatile("cp.async.cg.shared.global [%0], [%1], 16;" :: "r"(dst), "l"(src));
}

// m16n8k8 tf32 mma, D/C fp32 (target-neutral PTX, works at sm_103)
#define MMA_TF32(d, A0, A1, A2, A3, B0, B1)                                   \
    asm volatile("mma.sync.aligned.m16n8k8.row.col.f32.tf32.tf32.f32 "        \
        "{%0,%1,%2,%3}, {%4,%5,%6,%7}, {%8,%9}, {%0,%1,%2,%3};"               \
        : "+f"((d)[0]), "+f"((d)[1]), "+f"((d)[2]), "+f"((d)[3])              \
        : "r"(A0), "r"(A1), "r"(A2), "r"(A3), "r"(B0), "r"(B1))

// ================================================================
// Kernel A: h = x @ W ; emits g_hc (chunk-interleaved tf32 hi-only),
// g_ssrc, g_sdst. Block = 32 rows, 256 threads, 96KB smem -> 2 CTA/SM.
// ================================================================
__global__ void __launch_bounds__(256, 2) gemm_h_kernel(const float* __restrict__ x,
                                                        const float* __restrict__ W,
                                                        const float* __restrict__ w2) {
    extern __shared__ float dynsm[];
    float* ws = dynsm;            // [256][64]  = 64KB
    float* xs = dynsm + 16384;    // [32][256]  = 32KB

    const int t    = threadIdx.x;
    const int rowg = t >> 4;      // 0..15 -> 2 rows each
    const int cg   = t & 15;      // 4 cols
    const long base_row = (long)blockIdx.x * 32;

    {
        const float4* wg  = (const float4*)W;
        float4*       ws4 = (float4*)ws;
        #pragma unroll
        for (int i = 0; i < 16; i++) ws4[t + i * 256] = wg[t + i * 256];
        const float4* xg  = (const float4*)(x + base_row * 256);
        float4*       xs4 = (float4*)xs;
        #pragma unroll
        for (int i = 0; i < 8; i++) xs4[t + i * 256] = xg[t + i * 256];
    }
    __syncthreads();

    ull acc2[2][2];
    #pragma unroll
    for (int r = 0; r < 2; r++) { acc2[r][0] = 0ULL; acc2[r][1] = 0ULL; }

    #pragma unroll 8
    for (int k = 0; k < 256; k++) {
        const ulonglong2 wv = *(const ulonglong2*)&ws[k * 64 + cg * 4];
        #pragma unroll
        for (int r = 0; r < 2; r++) {
            const float xv = xs[(rowg * 2 + r) * 256 + k];
            const ull x2 = pack2(xv, xv);
            acc2[r][0] = fma2(wv.x, x2, acc2[r][0]);
            acc2[r][1] = fma2(wv.y, x2, acc2[r][1]);
        }
    }

    float av[2][4];
    const float4 as = *(const float4*)(w2 + cg * 4);
    const float4 ad = *(const float4*)(w2 + 64 + cg * 4);
    #pragma unroll
    for (int r = 0; r < 2; r++) {
        unpack2(acc2[r][0], av[r][0], av[r][1]);
        unpack2(acc2[r][1], av[r][2], av[r][3]);
        float ps = av[r][0] * as.x + av[r][1] * as.y + av[r][2] * as.z + av[r][3] * as.w;
        float pd = av[r][0] * ad.x + av[r][1] * ad.y + av[r][2] * ad.z + av[r][3] * ad.w;
        #pragma unroll
        for (int o = 1; o < 16; o <<= 1) {
            ps += __shfl_xor_sync(0xffffffffu, ps, o);
            pd += __shfl_xor_sync(0xffffffffu, pd, o);
        }
        if (cg == 0) {
            g_ssrc[base_row + rowg * 2 + r] = ps;
            g_sdst[base_row + rowg * 2 + r] = pd;
        }
    }

    // stage h rows (local 0..31) into smem, then emit tf32 hi-only pairs
    __syncthreads();              // k-loop readers of ws/xs done
    float* h_sm = dynsm;          // [32][65]
    #pragma unroll
    for (int r = 0; r < 2; r++)
        #pragma unroll
        for (int u = 0; u < 4; u++)
            h_sm[(rowg * 2 + r) * 65 + cg * 4 + u] = av[r][u];
    __syncthreads();

    const int b     = (int)(base_row >> 11);
    const int ck    = (int)((base_row & 2047) >> 6);
    const int jhalf = (int)((base_row >> 5) & 1);   // which 32-j half of chunk
    float* dst = g_hc + ((long)b * 32 + ck) * 4096;
    // this block covers kt_global = jhalf*4 .. +3 : 1024 float2 pieces
    #pragma unroll
    for (int it = 0; it < 4; it++) {
        const int f2l = t + it * 256;        // 0..1023
        const int ktl = f2l >> 8;            // 0..3
        const int c   = (f2l >> 2) & 63;
        const int q   = f2l & 3;
        const int jl  = ktl * 8 + q;         // local row (0..27, +4 -> 31)
        const float hA = h_sm[jl * 65 + c];
        const float hB = h_sm[(jl + 4) * 65 + c];
        const int fi = (jhalf * 4 + ktl) * 512 + c * 8 + q * 2;
        *(float2*)(dst + fi) = make_float2(rna_tf32(hA), rna_tf32(hB));
    }
}

// ================================================================
// Kernel B: masked softmax + P@V on tensor cores (mma.sync tf32).
// CTA = 128 rows, 256 threads, 8 warps x 16 rows; 3 CTAs/SM (68KB smem).
// H chunks (hi-only tf32, 16KB) double-buffered via cp.async.
// Per chunk: score (p~ = tf32(exp(relu)) or 0 -> psm, l += p~),
// then 8kt x 8nt m16n8k8 MMAs per warp (single plane).
// ================================================================
__global__ void __launch_bounds__(256, 3) attn_kernel(const int* __restrict__ adj,
                                                      float* __restrict__ out) {
    extern __shared__ float sm[];
    float* psm = sm;                 // [128][68]  34816B
    float* hs  = sm + 128 * 68;      // [2][4096]  32768B
    float* lsm = hs + 2 * 4096;      // [128]      512B

    const int t  = threadIdx.x;
    const int ln = t & 31;
    const int w  = t >> 5;
    const int b  = blockIdx.y;
    const int ib = blockIdx.x * 128;
    const long bn = (long)b * 2048;
    const int R0 = w * 16;           // warp row base

    // score-phase decomposition: rows rh+2i (i=0..7), j's u*4..+3
    const int u  = ln & 15;
    const int rh = ln >> 4;
    // mma-phase decomposition
    const int q  = ln & 3;
    const int r4 = ln >> 2;

    float ssrcv[8];
    #pragma unroll
    for (int i = 0; i < 8; i++)
        ssrcv[i] = g_ssrc[bn + ib + R0 + rh + 2 * i];

    const int*    adjp  = adj + (bn + ib + R0 + rh) * 2048 + u * 4;
    const float4* hsrc4 = (const float4*)(g_hc + (long)b * 32 * 4096);
    const uint    hs_u  = smem_u32(hs);

    float acc[8][4];
    #pragma unroll
    for (int nt = 0; nt < 8; nt++)
        #pragma unroll
        for (int e = 0; e < 4; e++) acc[nt][e] = 0.f;
    float lpart[8];
    #pragma unroll
    for (int i = 0; i < 8; i++) lpart[i] = 0.f;

    // prologue: stream chunk 0 into buf 0 (1024 float4)
    #pragma unroll
    for (int it = 0; it < 4; it++)
        cpasync16(hs_u + (uint)(t + it * 256) * 16, hsrc4 + t + it * 256);
    asm volatile("cp.async.commit_group;" ::: "memory");

    for (int ck = 0; ck < 32; ck++) {
        const int buf = ck & 1;
        const int jc  = ck * 64;
        __syncthreads();             // prev mma readers of psm/hs[buf^1] done
        if (ck < 31) {               // stream next chunk into the other buffer
            const float4* s = hsrc4 + (ck + 1) * 1024;
            const uint d = hs_u + (uint)(buf ^ 1) * 16384;
            #pragma unroll
            for (int it = 0; it < 4; it++)
                cpasync16(d + (uint)(t + it * 256) * 16, s + t + it * 256);
            asm volatile("cp.async.commit_group;" ::: "memory");
        }

        // ---- score phase (independent of hs) ----
        const float4 sd = *((const float4*)(g_sdst + bn + jc) + u);
        #pragma unroll
        for (int i = 0; i < 8; i++) {
            const int4 a = *(const int4*)(adjp + (long)(2 * i) * 2048 + jc);
            const float p0 = (a.x > 0) ? rna_tf32(__expf(fmaxf(ssrcv[i] + sd.x, 0.f))) : 0.f;
            const float p1 = (a.y > 0) ? rna_tf32(__expf(fmaxf(ssrcv[i] + sd.y, 0.f))) : 0.f;
            const float p2 = (a.z > 0) ? rna_tf32(__expf(fmaxf(ssrcv[i] + sd.z, 0.f))) : 0.f;
            const float p3 = (a.w > 0) ? rna_tf32(__expf(fmaxf(ssrcv[i] + sd.w, 0.f))) : 0.f;
            lpart[i] += (p0 + p1) + (p2 + p3);
            *(float4*)&psm[(R0 + rh + 2 * i) * 68 + u * 4] = make_float4(p0, p1, p2, p3);
        }

        if (ck < 31) asm volatile("cp.async.wait_group 1;" ::: "memory");
        else         asm volatile("cp.async.wait_group 0;" ::: "memory");
        __syncthreads();             // psm + hs[buf] visible

        // ---- mma phase: 8 kt x 8 nt (hi-only) ----
        const float* hb = hs + buf * 4096;
        #pragma unroll
        for (int kt = 0; kt < 8; kt++) {
            const int pcol = kt * 8 + q;
            const uint A0 = __float_as_uint(psm[(R0 + r4) * 68 + pcol]);
            const uint A1 = __float_as_uint(psm[(R0 + r4 + 8) * 68 + pcol]);
            const uint A2 = __float_as_uint(psm[(R0 + r4) * 68 + pcol + 4]);
            const uint A3 = __float_as_uint(psm[(R0 + r4 + 8) * 68 + pcol + 4]);
            #pragma unroll
            for (int nt = 0; nt < 8; nt++) {
                const int c = nt * 8 + r4;
                const float2 bq = *(const float2*)&hb[kt * 512 + c * 8 + q * 2];
                MMA_TF32(acc[nt], A0, A1, A2, A3,
                         __float_as_uint(bq.x), __float_as_uint(bq.y));
            }
        }
    }

    // ---- l: reduce over the 16 u-lanes of each rh half ----
    #pragma unroll
    for (int o = 1; o < 16; o <<= 1)
        #pragma unroll
        for (int i = 0; i < 8; i++)
            lpart[i] += __shfl_xor_sync(0xffffffffu, lpart[i], o);
    if (ln == 0) {
        #pragma unroll
        for (int i = 0; i < 8; i++) lsm[R0 + 2 * i] = lpart[i];
    } else if (ln == 16) {
        #pragma unroll
        for (int i = 0; i < 8; i++) lsm[R0 + 2 * i + 1] = lpart[i];
    }
    __syncwarp();

    // ---- epilogue ----
    const float inv0 = 1.f / lsm[R0 + r4];
    const float inv1 = 1.f / lsm[R0 + r4 + 8];
    const long row0 = bn + ib + R0 + r4;
    #pragma unroll
    for (int nt = 0; nt < 8; nt++) {
        *(float2*)(out + row0 * 64 + nt * 8 + 2 * q) =
            make_float2(acc[nt][0] * inv0, acc[nt][1] * inv0);
        *(float2*)(out + (row0 + 8) * 64 + nt * 8 + 2 * q) =
            make_float2(acc[nt][2] * inv1, acc[nt][3] * inv1);
    }
}

// ================================================================
// launch
// inputs: x f32[16,2048,256], adj i32[16,2048,2048],
//         weight f32[256,64], weight2 f32[128,1]
// output: f32[16,2048,64]
// ================================================================
extern "C" void kernel_launch(void* const* d_in, const int* in_sizes, int n_in,
                              void* d_out, int out_size) {
    const float* x   = (const float*)d_in[0];
    const int*   adj = (const int*)d_in[1];
    const float* W   = (const float*)d_in[2];
    const float* w2  = (const float*)d_in[3];
    float* out = (float*)d_out;

    cudaFuncSetAttribute(gemm_h_kernel,
                         cudaFuncAttributeMaxDynamicSharedMemorySize, 98304);
    cudaFuncSetAttribute(attn_kernel,
                         cudaFuncAttributeMaxDynamicSharedMemorySize, 68096);

    gemm_h_kernel<<<1024, 256, 98304>>>(x, W, w2);        // 32 rows/block
    attn_kernel<<<dim3(16, 16), 256, 68096>>>(adj, out);  // 128 rows/CTA
}

// round 11
// speedup vs baseline: 1.6589x; 1.6589x over previous
#include <cuda_runtime.h>
#include <math.h>
#include <stdint.h>

typedef unsigned long long ull;
typedef unsigned int uint;

// ---------------- scratch (no allocations allowed) ----------------
// g_hc[b][chunk][4096]: per 64-j chunk, tf32 (hi-only) interleaved:
//   float index = kt*512 + c*8 + q*2 + s,  s=0: h[j=8kt+q][c], s=1: h[j=8kt+q+4][c]
__device__ float g_hc[16 * 32 * 4096];    // 8.4 MB
__device__ float g_ssrc[16 * 2048];
__device__ float g_sdst[16 * 2048];

// ---------------- helpers ----------------
__device__ __forceinline__ uint smem_u32(const void* p) {
    uint a;
    asm("{ .reg .u64 t; cvta.to.shared.u64 t, %1; cvt.u32.u64 %0, t; }" : "=r"(a) : "l"(p));
    return a;
}
__device__ __forceinline__ ull pack2(float lo, float hi) {
    ull r; asm("mov.b64 %0, {%1, %2};" : "=l"(r) : "f"(lo), "f"(hi)); return r;
}
__device__ __forceinline__ void unpack2(ull v, float& lo, float& hi) {
    asm("mov.b64 {%0, %1}, %2;" : "=f"(lo), "=f"(hi) : "l"(v));
}
__device__ __forceinline__ ull fma2(ull a, ull b, ull c) {
    ull d; asm("fma.rn.f32x2 %0, %1, %2, %3;" : "=l"(d) : "l"(a), "l"(b), "l"(c)); return d;
}
__device__ __forceinline__ float rna_tf32(float x) {
    float r; asm("cvt.rna.tf32.f32 %0, %1;" : "=f"(r) : "f"(x)); return r;
}
__device__ __forceinline__ void cpasync16(uint dst, const void* src) {
    asm volatile("cp.async.cg.shared.global [%0], [%1], 16;" :: "r"(dst), "l"(src));
}

// m16n8k8 tf32 mma, D/C fp32 (target-neutral PTX, works at sm_103)
#define MMA_TF32(d, A0, A1, A2, A3, B0, B1)                                   \
    asm volatile("mma.sync.aligned.m16n8k8.row.col.f32.tf32.tf32.f32 "        \
        "{%0,%1,%2,%3}, {%4,%5,%6,%7}, {%8,%9}, {%0,%1,%2,%3};"               \
        : "+f"((d)[0]), "+f"((d)[1]), "+f"((d)[2]), "+f"((d)[3])              \
        : "r"(A0), "r"(A1), "r"(A2), "r"(A3), "r"(B0), "r"(B1))

// ================================================================
// Kernel A: h = x @ W ; emits g_hc (chunk-interleaved tf32 hi-only),
// g_ssrc, g_sdst. Block = 32 rows, 256 threads, 96KB smem -> 2 CTA/SM.
// ================================================================
__global__ void __launch_bounds__(256, 2) gemm_h_kernel(const float* __restrict__ x,
                                                        const float* __restrict__ W,
                                                        const float* __restrict__ w2) {
    extern __shared__ float dynsm[];
    float* ws = dynsm;            // [256][64]  = 64KB
    float* xs = dynsm + 16384;    // [32][256]  = 32KB

    const int t    = threadIdx.x;
    const int rowg = t >> 4;      // 0..15 -> 2 rows each
    const int cg   = t & 15;      // 4 cols
    const long base_row = (long)blockIdx.x * 32;

    {
        const float4* wg  = (const float4*)W;
        float4*       ws4 = (float4*)ws;
        #pragma unroll
        for (int i = 0; i < 16; i++) ws4[t + i * 256] = wg[t + i * 256];
        const float4* xg  = (const float4*)(x + base_row * 256);
        float4*       xs4 = (float4*)xs;
        #pragma unroll
        for (int i = 0; i < 8; i++) xs4[t + i * 256] = xg[t + i * 256];
    }
    __syncthreads();

    ull acc2[2][2];
    #pragma unroll
    for (int r = 0; r < 2; r++) { acc2[r][0] = 0ULL; acc2[r][1] = 0ULL; }

    #pragma unroll 8
    for (int k = 0; k < 256; k++) {
        const ulonglong2 wv = *(const ulonglong2*)&ws[k * 64 + cg * 4];
        #pragma unroll
        for (int r = 0; r < 2; r++) {
            const float xv = xs[(rowg * 2 + r) * 256 + k];
            const ull x2 = pack2(xv, xv);
            acc2[r][0] = fma2(wv.x, x2, acc2[r][0]);
            acc2[r][1] = fma2(wv.y, x2, acc2[r][1]);
        }
    }

    float av[2][4];
    const float4 as = *(const float4*)(w2 + cg * 4);
    const float4 ad = *(const float4*)(w2 + 64 + cg * 4);
    #pragma unroll
    for (int r = 0; r < 2; r++) {
        unpack2(acc2[r][0], av[r][0], av[r][1]);
        unpack2(acc2[r][1], av[r][2], av[r][3]);
        float ps = av[r][0] * as.x + av[r][1] * as.y + av[r][2] * as.z + av[r][3] * as.w;
        float pd = av[r][0] * ad.x + av[r][1] * ad.y + av[r][2] * ad.z + av[r][3] * ad.w;
        #pragma unroll
        for (int o = 1; o < 16; o <<= 1) {
            ps += __shfl_xor_sync(0xffffffffu, ps, o);
            pd += __shfl_xor_sync(0xffffffffu, pd, o);
        }
        if (cg == 0) {
            g_ssrc[base_row + rowg * 2 + r] = ps;
            g_sdst[base_row + rowg * 2 + r] = pd;
        }
    }

    // stage h rows (local 0..31) into smem, then emit tf32 hi-only pairs
    __syncthreads();              // k-loop readers of ws/xs done
    float* h_sm = dynsm;          // [32][65]
    #pragma unroll
    for (int r = 0; r < 2; r++)
        #pragma unroll
        for (int u = 0; u < 4; u++)
            h_sm[(rowg * 2 + r) * 65 + cg * 4 + u] = av[r][u];
    __syncthreads();

    const int b     = (int)(base_row >> 11);
    const int ck    = (int)((base_row & 2047) >> 6);
    const int jhalf = (int)((base_row >> 5) & 1);   // which 32-j half of chunk
    float* dst = g_hc + ((long)b * 32 + ck) * 4096;
    // this block covers kt_global = jhalf*4 .. +3 : 1024 float2 pieces
    #pragma unroll
    for (int it = 0; it < 4; it++) {
        const int f2l = t + it * 256;        // 0..1023
        const int ktl = f2l >> 8;            // 0..3
        const int c   = (f2l >> 2) & 63;
        const int q   = f2l & 3;
        const int jl  = ktl * 8 + q;         // local row
        const float hA = h_sm[jl * 65 + c];
        const float hB = h_sm[(jl + 4) * 65 + c];
        const int fi = (jhalf * 4 + ktl) * 512 + c * 8 + q * 2;
        *(float2*)(dst + fi) = make_float2(rna_tf32(hA), rna_tf32(hB));
    }
}

// ================================================================
// Kernel B: masked softmax + P@V on tensor cores (mma.sync tf32).
// CTA = 128 rows, 256 threads, 8 warps x 16 rows; 2 CTAs/SM.
// Both streams staged via cp.async, overlapped with compute:
//   adj: single 32KB buffer, chunk ck+1 prefetched during mma(ck)
//   H:   double-buffered 2x16KB (hi-only tf32)
// Per chunk: score (reads adj from smem; p~ = tf32(exp(relu)) or 0),
// then 8kt x 8nt m16n8k8 MMAs per warp.
// ================================================================
__global__ void __launch_bounds__(256, 2) attn_kernel(const int* __restrict__ adj,
                                                      float* __restrict__ out) {
    extern __shared__ float sm[];
    float* psm    = sm;                  // [128][68]  34816B
    float* hs     = sm + 128 * 68;       // [2][4096]  32768B
    int*   adj_sm = (int*)(hs + 8192);   // [128][64]  32768B
    float* lsm    = (float*)(adj_sm + 8192);  // [128]  512B

    const int t  = threadIdx.x;
    const int ln = t & 31;
    const int w  = t >> 5;
    const int b  = blockIdx.y;
    const int ib = blockIdx.x * 128;
    const long bn = (long)b * 2048;
    const int R0 = w * 16;           // warp row base

    // score-phase decomposition: rows rh+2i (i=0..7), j's u*4..+3
    const int u  = ln & 15;
    const int rh = ln >> 4;
    // mma-phase decomposition
    const int q  = ln & 3;
    const int r4 = ln >> 2;

    float ssrcv[8];
    #pragma unroll
    for (int i = 0; i < 8; i++)
        ssrcv[i] = g_ssrc[bn + ib + R0 + rh + 2 * i];

    const int*    adjg  = adj + (bn + ib) * 2048;        // CTA's adj base
    const float4* hsrc4 = (const float4*)(g_hc + (long)b * 32 * 4096);
    const uint    hs_u  = smem_u32(hs);
    const uint    adj_u = smem_u32(adj_sm);
    const int4*   adj_sm4 = (const int4*)adj_sm;

    float acc[8][4];
    #pragma unroll
    for (int nt = 0; nt < 8; nt++)
        #pragma unroll
        for (int e = 0; e < 4; e++) acc[nt][e] = 0.f;
    float lpart[8];
    #pragma unroll
    for (int i = 0; i < 8; i++) lpart[i] = 0.f;

    // prologue: stream H[0] -> hs[0] and adj[0] -> adj_sm
    #pragma unroll
    for (int it = 0; it < 4; it++)
        cpasync16(hs_u + (uint)(t + it * 256) * 16, hsrc4 + t + it * 256);
    #pragma unroll
    for (int it = 0; it < 8; it++) {
        const int s = t + it * 256;          // 16B segment: row = s>>4, c16 = s&15
        cpasync16(adj_u + (uint)s * 16, adjg + (long)(s >> 4) * 2048 + (s & 15) * 4);
    }
    asm volatile("cp.async.commit_group;" ::: "memory");
    asm volatile("cp.async.wait_group 0;" ::: "memory");
    __syncthreads();

    for (int ck = 0; ck < 32; ck++) {
        const int buf = ck & 1;
        const int jc  = ck * 64;

        // ---- score phase: adj from smem, sdst from L2 ----
        const float4 sd = *((const float4*)(g_sdst + bn + jc) + u);
        #pragma unroll
        for (int i = 0; i < 8; i++) {
            const int row = R0 + rh + 2 * i;
            const int4 a = adj_sm4[row * 16 + u];
            const float p0 = (a.x > 0) ? rna_tf32(__expf(fmaxf(ssrcv[i] + sd.x, 0.f))) : 0.f;
            const float p1 = (a.y > 0) ? rna_tf32(__expf(fmaxf(ssrcv[i] + sd.y, 0.f))) : 0.f;
            const float p2 = (a.z > 0) ? rna_tf32(__expf(fmaxf(ssrcv[i] + sd.z, 0.f))) : 0.f;
            const float p3 = (a.w > 0) ? rna_tf32(__expf(fmaxf(ssrcv[i] + sd.w, 0.f))) : 0.f;
            lpart[i] += (p0 + p1) + (p2 + p3);
            *(float4*)&psm[row * 68 + u * 4] = make_float4(p0, p1, p2, p3);
        }
        __syncthreads();             // psm ready; adj_sm fully consumed

        // ---- prefetch chunk ck+1 (adj + H) under the mma phase ----
        if (ck < 31) {
            #pragma unroll
            for (int it = 0; it < 8; it++) {
                const int s = t + it * 256;
                cpasync16(adj_u + (uint)s * 16,
                          adjg + (long)(s >> 4) * 2048 + (jc + 64) + (s & 15) * 4);
            }
            const float4* hsv = hsrc4 + (ck + 1) * 1024;
            const uint d = hs_u + (uint)(buf ^ 1) * 16384;
            #pragma unroll
            for (int it = 0; it < 4; it++)
                cpasync16(d + (uint)(t + it * 256) * 16, hsv + t + it * 256);
            asm volatile("cp.async.commit_group;" ::: "memory");
        }

        // ---- mma phase: 8 kt x 8 nt (hi-only) ----
        const float* hb = hs + buf * 4096;
        #pragma unroll
        for (int kt = 0; kt < 8; kt++) {
            const int pcol = kt * 8 + q;
            const uint A0 = __float_as_uint(psm[(R0 + r4) * 68 + pcol]);
            const uint A1 = __float_as_uint(psm[(R0 + r4 + 8) * 68 + pcol]);
            const uint A2 = __float_as_uint(psm[(R0 + r4) * 68 + pcol + 4]);
            const uint A3 = __float_as_uint(psm[(R0 + r4 + 8) * 68 + pcol + 4]);
            #pragma unroll
            for (int nt = 0; nt < 8; nt++) {
                const int c = nt * 8 + r4;
                const float2 bq = *(const float2*)&hb[kt * 512 + c * 8 + q * 2];
                MMA_TF32(acc[nt], A0, A1, A2, A3,
                         __float_as_uint(bq.x), __float_as_uint(bq.y));
            }
        }

        if (ck < 31) asm volatile("cp.async.wait_group 0;" ::: "memory");
        __syncthreads();             // mma readers done; next chunk staged
    }

    // ---- l: reduce over the 16 u-lanes of each rh half ----
    #pragma unroll
    for (int o = 1; o < 16; o <<= 1)
        #pragma unroll
        for (int i = 0; i < 8; i++)
            lpart[i] += __shfl_xor_sync(0xffffffffu, lpart[i], o);
    if (ln == 0) {
        #pragma unroll
        for (int i = 0; i < 8; i++) lsm[R0 + 2 * i] = lpart[i];
    } else if (ln == 16) {
        #pragma unroll
        for (int i = 0; i < 8; i++) lsm[R0 + 2 * i + 1] = lpart[i];
    }
    __syncwarp();

    // ---- epilogue ----
    const float inv0 = 1.f / lsm[R0 + r4];
    const float inv1 = 1.f / lsm[R0 + r4 + 8];
    const long row0 = bn + ib + R0 + r4;
    #pragma unroll
    for (int nt = 0; nt < 8; nt++) {
        *(float2*)(out + row0 * 64 + nt * 8 + 2 * q) =
            make_float2(acc[nt][0] * inv0, acc[nt][1] * inv0);
        *(float2*)(out + (row0 + 8) * 64 + nt * 8 + 2 * q) =
            make_float2(acc[nt][2] * inv1, acc[nt][3] * inv1);
    }
}

// ================================================================
// launch
// inputs: x f32[16,2048,256], adj i32[16,2048,2048],
//         weight f32[256,64], weight2 f32[128,1]
// output: f32[16,2048,64]
// ================================================================
extern "C" void kernel_launch(void* const* d_in, const int* in_sizes, int n_in,
                              void* d_out, int out_size) {
    const float* x   = (const float*)d_in[0];
    const int*   adj = (const int*)d_in[1];
    const float* W   = (const float*)d_in[2];
    const float* w2  = (const float*)d_in[3];
    float* out = (float*)d_out;

    cudaFuncSetAttribute(gemm_h_kernel,
                         cudaFuncAttributeMaxDynamicSharedMemorySize, 98304);
    cudaFuncSetAttribute(attn_kernel,
                         cudaFuncAttributeMaxDynamicSharedMemorySize, 100864);

    gemm_h_kernel<<<1024, 256, 98304>>>(x, W, w2);         // 32 rows/block
    attn_kernel<<<dim3(16, 16), 256, 100864>>>(adj, out);  // 128 rows/CTA
}

// round 12
// speedup vs baseline: 2.2051x; 1.3292x over previous
#include <cuda_runtime.h>
#include <math.h>
#include <stdint.h>

typedef unsigned long long ull;
typedef unsigned int uint;

// ---------------- scratch (no allocations allowed) ----------------
// g_hc[b][chunk][4096]: per 64-j chunk, tf32 (hi-only) interleaved:
//   float index = kt*512 + c*8 + q*2 + s,  s=0: h[j=8kt+q][c], s=1: h[j=8kt+q+4][c]
__device__ float g_hc[16 * 32 * 4096];    // 8.4 MB
__device__ float g_esrc[16 * 2048];       // exp(s_src)
__device__ float g_edst[16 * 2048];       // exp(s_dst)

// ---------------- helpers ----------------
__device__ __forceinline__ uint smem_u32(const void* p) {
    uint a;
    asm("{ .reg .u64 t; cvta.to.shared.u64 t, %1; cvt.u32.u64 %0, t; }" : "=r"(a) : "l"(p));
    return a;
}
__device__ __forceinline__ ull pack2(float lo, float hi) {
    ull r; asm("mov.b64 %0, {%1, %2};" : "=l"(r) : "f"(lo), "f"(hi)); return r;
}
__device__ __forceinline__ void unpack2(ull v, float& lo, float& hi) {
    asm("mov.b64 {%0, %1}, %2;" : "=f"(lo), "=f"(hi) : "l"(v));
}
__device__ __forceinline__ ull fma2(ull a, ull b, ull c) {
    ull d; asm("fma.rn.f32x2 %0, %1, %2, %3;" : "=l"(d) : "l"(a), "l"(b), "l"(c)); return d;
}
__device__ __forceinline__ float rna_tf32(float x) {
    float r; asm("cvt.rna.tf32.f32 %0, %1;" : "=f"(r) : "f"(x)); return r;
}
__device__ __forceinline__ void cpasync16(uint dst, const void* src) {
    asm volatile("cp.async.cg.shared.global [%0], [%1], 16;" :: "r"(dst), "l"(src));
}

// m16n8k8 tf32 mma, D/C fp32 (target-neutral PTX, works at sm_103)
#define MMA_TF32(d, A0, A1, A2, A3, B0, B1)                                   \
    asm volatile("mma.sync.aligned.m16n8k8.row.col.f32.tf32.tf32.f32 "        \
        "{%0,%1,%2,%3}, {%4,%5,%6,%7}, {%8,%9}, {%0,%1,%2,%3};"               \
        : "+f"((d)[0]), "+f"((d)[1]), "+f"((d)[2]), "+f"((d)[3])              \
        : "r"(A0), "r"(A1), "r"(A2), "r"(A3), "r"(B0), "r"(B1))

// ================================================================
// Kernel A: h = x @ W ; emits g_hc (chunk-interleaved tf32 hi-only),
// g_esrc = exp(s_src), g_edst = exp(s_dst).
// Block = 32 rows, 256 threads, 96KB smem -> 2 CTA/SM.
// ================================================================
__global__ void __launch_bounds__(256, 2) gemm_h_kernel(const float* __restrict__ x,
                                                        const float* __restrict__ W,
                                                        const float* __restrict__ w2) {
    extern __shared__ float dynsm[];
    float* ws = dynsm;            // [256][64]  = 64KB
    float* xs = dynsm + 16384;    // [32][256]  = 32KB

    const int t    = threadIdx.x;
    const int rowg = t >> 4;      // 0..15 -> 2 rows each
    const int cg   = t & 15;      // 4 cols
    const long base_row = (long)blockIdx.x * 32;

    {
        const float4* wg  = (const float4*)W;
        float4*       ws4 = (float4*)ws;
        #pragma unroll
        for (int i = 0; i < 16; i++) ws4[t + i * 256] = wg[t + i * 256];
        const float4* xg  = (const float4*)(x + base_row * 256);
        float4*       xs4 = (float4*)xs;
        #pragma unroll
        for (int i = 0; i < 8; i++) xs4[t + i * 256] = xg[t + i * 256];
    }
    __syncthreads();

    ull acc2[2][2];
    #pragma unroll
    for (int r = 0; r < 2; r++) { acc2[r][0] = 0ULL; acc2[r][1] = 0ULL; }

    #pragma unroll 8
    for (int k = 0; k < 256; k++) {
        const ulonglong2 wv = *(const ulonglong2*)&ws[k * 64 + cg * 4];
        #pragma unroll
        for (int r = 0; r < 2; r++) {
            const float xv = xs[(rowg * 2 + r) * 256 + k];
            const ull x2 = pack2(xv, xv);
            acc2[r][0] = fma2(wv.x, x2, acc2[r][0]);
            acc2[r][1] = fma2(wv.y, x2, acc2[r][1]);
        }
    }

    float av[2][4];
    const float4 as = *(const float4*)(w2 + cg * 4);
    const float4 ad = *(const float4*)(w2 + 64 + cg * 4);
    #pragma unroll
    for (int r = 0; r < 2; r++) {
        unpack2(acc2[r][0], av[r][0], av[r][1]);
        unpack2(acc2[r][1], av[r][2], av[r][3]);
        float ps = av[r][0] * as.x + av[r][1] * as.y + av[r][2] * as.z + av[r][3] * as.w;
        float pd = av[r][0] * ad.x + av[r][1] * ad.y + av[r][2] * ad.z + av[r][3] * ad.w;
        #pragma unroll
        for (int o = 1; o < 16; o <<= 1) {
            ps += __shfl_xor_sync(0xffffffffu, ps, o);
            pd += __shfl_xor_sync(0xffffffffu, pd, o);
        }
        if (cg == 0) {
            g_esrc[base_row + rowg * 2 + r] = __expf(ps);
            g_edst[base_row + rowg * 2 + r] = __expf(pd);
        }
    }

    // stage h rows (local 0..31) into smem, then emit tf32 hi-only pairs
    __syncthreads();              // k-loop readers of ws/xs done
    float* h_sm = dynsm;          // [32][65]
    #pragma unroll
    for (int r = 0; r < 2; r++)
        #pragma unroll
        for (int u = 0; u < 4; u++)
            h_sm[(rowg * 2 + r) * 65 + cg * 4 + u] = av[r][u];
    __syncthreads();

    const int b     = (int)(base_row >> 11);
    const int ck    = (int)((base_row & 2047) >> 6);
    const int jhalf = (int)((base_row >> 5) & 1);   // which 32-j half of chunk
    float* dst = g_hc + ((long)b * 32 + ck) * 4096;
    // this block covers kt_global = jhalf*4 .. +3 : 1024 float2 pieces
    #pragma unroll
    for (int it = 0; it < 4; it++) {
        const int f2l = t + it * 256;        // 0..1023
        const int ktl = f2l >> 8;            // 0..3
        const int c   = (f2l >> 2) & 63;
        const int q   = f2l & 3;
        const int jl  = ktl * 8 + q;         // local row
        const float hA = h_sm[jl * 65 + c];
        const float hB = h_sm[(jl + 4) * 65 + c];
        const int fi = (jhalf * 4 + ktl) * 512 + c * 8 + q * 2;
        *(float2*)(dst + fi) = make_float2(rna_tf32(hA), rna_tf32(hB));
    }
}

// ================================================================
// Kernel B: masked softmax + P@V on tensor cores (mma.sync tf32).
// CTA = 128 rows, 256 threads, 8 warps x 16 rows; 2 CTAs/SM.
// Score phase is exp-free:
//   exp(relu(ssrc+sdst)) = max(exp(ssrc)*exp(sdst), 1)
// with e_src/e_dst precomputed by the gemm kernel. So:
//   p~ = adj>0 ? tf32(fmax(esrc*edst, 1)) : 0,  l += p~
// adj staged via cp.async (32KB, prefetched under mma); H hi-only
// tf32 double-buffered 2x16KB. Then 8kt x 8nt m16n8k8 per warp.
// ================================================================
__global__ void __launch_bounds__(256, 2) attn_kernel(const int* __restrict__ adj,
                                                      float* __restrict__ out) {
    extern __shared__ float sm[];
    float* psm    = sm;                  // [128][68]  34816B
    float* hs     = sm + 128 * 68;       // [2][4096]  32768B
    int*   adj_sm = (int*)(hs + 8192);   // [128][64]  32768B
    float* lsm    = (float*)(adj_sm + 8192);  // [128]  512B

    const int t  = threadIdx.x;
    const int ln = t & 31;
    const int w  = t >> 5;
    const int b  = blockIdx.y;
    const int ib = blockIdx.x * 128;
    const long bn = (long)b * 2048;
    const int R0 = w * 16;           // warp row base

    // score-phase decomposition: rows rh+2i (i=0..7), j's u*4..+3
    const int u  = ln & 15;
    const int rh = ln >> 4;
    // mma-phase decomposition
    const int q  = ln & 3;
    const int r4 = ln >> 2;

    float esrcv[8];
    #pragma unroll
    for (int i = 0; i < 8; i++)
        esrcv[i] = g_esrc[bn + ib + R0 + rh + 2 * i];

    const int*    adjg  = adj + (bn + ib) * 2048;        // CTA's adj base
    const float4* hsrc4 = (const float4*)(g_hc + (long)b * 32 * 4096);
    const uint    hs_u  = smem_u32(hs);
    const uint    adj_u = smem_u32(adj_sm);
    const int4*   adj_sm4 = (const int4*)adj_sm;

    float acc[8][4];
    #pragma unroll
    for (int nt = 0; nt < 8; nt++)
        #pragma unroll
        for (int e = 0; e < 4; e++) acc[nt][e] = 0.f;
    float lpart[8];
    #pragma unroll
    for (int i = 0; i < 8; i++) lpart[i] = 0.f;

    // prologue: stream H[0] -> hs[0] and adj[0] -> adj_sm
    #pragma unroll
    for (int it = 0; it < 4; it++)
        cpasync16(hs_u + (uint)(t + it * 256) * 16, hsrc4 + t + it * 256);
    #pragma unroll
    for (int it = 0; it < 8; it++) {
        const int s = t + it * 256;          // 16B segment: row = s>>4, c16 = s&15
        cpasync16(adj_u + (uint)s * 16, adjg + (long)(s >> 4) * 2048 + (s & 15) * 4);
    }
    asm volatile("cp.async.commit_group;" ::: "memory");
    asm volatile("cp.async.wait_group 0;" ::: "memory");
    __syncthreads();

    for (int ck = 0; ck < 32; ck++) {
        const int buf = ck & 1;
        const int jc  = ck * 64;

        // ---- score phase: p = adj ? tf32(max(esrc*edst, 1)) : 0 ----
        const float4 ed = *((const float4*)(g_edst + bn + jc) + u);
        #pragma unroll
        for (int i = 0; i < 8; i++) {
            const int row = R0 + rh + 2 * i;
            const int4 a = adj_sm4[row * 16 + u];
            const float es = esrcv[i];
            const float p0 = (a.x > 0) ? rna_tf32(fmaxf(es * ed.x, 1.f)) : 0.f;
            const float p1 = (a.y > 0) ? rna_tf32(fmaxf(es * ed.y, 1.f)) : 0.f;
            const float p2 = (a.z > 0) ? rna_tf32(fmaxf(es * ed.z, 1.f)) : 0.f;
            const float p3 = (a.w > 0) ? rna_tf32(fmaxf(es * ed.w, 1.f)) : 0.f;
            lpart[i] += (p0 + p1) + (p2 + p3);
            *(float4*)&psm[row * 68 + u * 4] = make_float4(p0, p1, p2, p3);
        }
        __syncthreads();             // psm ready; adj_sm fully consumed

        // ---- prefetch chunk ck+1 (adj + H) under the mma phase ----
        if (ck < 31) {
            #pragma unroll
            for (int it = 0; it < 8; it++) {
                const int s = t + it * 256;
                cpasync16(adj_u + (uint)s * 16,
                          adjg + (long)(s >> 4) * 2048 + (jc + 64) + (s & 15) * 4);
            }
            const float4* hsv = hsrc4 + (ck + 1) * 1024;
            const uint d = hs_u + (uint)(buf ^ 1) * 16384;
            #pragma unroll
            for (int it = 0; it < 4; it++)
                cpasync16(d + (uint)(t + it * 256) * 16, hsv + t + it * 256);
            asm volatile("cp.async.commit_group;" ::: "memory");
        }

        // ---- mma phase: 8 kt x 8 nt (hi-only) ----
        const float* hb = hs + buf * 4096;
        #pragma unroll
        for (int kt = 0; kt < 8; kt++) {
            const int pcol = kt * 8 + q;
            const uint A0 = __float_as_uint(psm[(R0 + r4) * 68 + pcol]);
            const uint A1 = __float_as_uint(psm[(R0 + r4 + 8) * 68 + pcol]);
            const uint A2 = __float_as_uint(psm[(R0 + r4) * 68 + pcol + 4]);
            const uint A3 = __float_as_uint(psm[(R0 + r4 + 8) * 68 + pcol + 4]);
            #pragma unroll
            for (int nt = 0; nt < 8; nt++) {
                const int c = nt * 8 + r4;
                const float2 bq = *(const float2*)&hb[kt * 512 + c * 8 + q * 2];
                MMA_TF32(acc[nt], A0, A1, A2, A3,
                         __float_as_uint(bq.x), __float_as_uint(bq.y));
            }
        }

        if (ck < 31) asm volatile("cp.async.wait_group 0;" ::: "memory");
        __syncthreads();             // mma readers done; next chunk staged
    }

    // ---- l: reduce over the 16 u-lanes of each rh half ----
    #pragma unroll
    for (int o = 1; o < 16; o <<= 1)
        #pragma unroll
        for (int i = 0; i < 8; i++)
            lpart[i] += __shfl_xor_sync(0xffffffffu, lpart[i], o);
    if (ln == 0) {
        #pragma unroll
        for (int i = 0; i < 8; i++) lsm[R0 + 2 * i] = lpart[i];
    } else if (ln == 16) {
        #pragma unroll
        for (int i = 0; i < 8; i++) lsm[R0 + 2 * i + 1] = lpart[i];
    }
    __syncwarp();

    // ---- epilogue ----
    const float inv0 = 1.f / lsm[R0 + r4];
    const float inv1 = 1.f / lsm[R0 + r4 + 8];
    const long row0 = bn + ib + R0 + r4;
    #pragma unroll
    for (int nt = 0; nt < 8; nt++) {
        *(float2*)(out + row0 * 64 + nt * 8 + 2 * q) =
            make_float2(acc[nt][0] * inv0, acc[nt][1] * inv0);
        *(float2*)(out + (row0 + 8) * 64 + nt * 8 + 2 * q) =
            make_float2(acc[nt][2] * inv1, acc[nt][3] * inv1);
    }
}

// ================================================================
// launch
// inputs: x f32[16,2048,256], adj i32[16,2048,2048],
//         weight f32[256,64], weight2 f32[128,1]
// output: f32[16,2048,64]
// ================================================================
extern "C" void kernel_launch(void* const* d_in, const int* in_sizes, int n_in,
                              void* d_out, int out_size) {
    const float* x   = (const float*)d_in[0];
    const int*   adj = (const int*)d_in[1];
    const float* W   = (const float*)d_in[2];
    const float* w2  = (const float*)d_in[3];
    float* out = (float*)d_out;

    cudaFuncSetAttribute(gemm_h_kernel,
                         cudaFuncAttributeMaxDynamicSharedMemorySize, 98304);
    cudaFuncSetAttribute(attn_kernel,
                         cudaFuncAttributeMaxDynamicSharedMemorySize, 100864);

    gemm_h_kernel<<<1024, 256, 98304>>>(x, W, w2);         // 32 rows/block
    attn_kernel<<<dim3(16, 16), 256, 100864>>>(adj, out);  // 128 rows/CTA
}

// round 14
// speedup vs baseline: 2.2707x; 1.0298x over previous
#include <cuda_runtime.h>
#include <math.h>
#include <stdint.h>

typedef unsigned long long ull;
typedef unsigned int uint;

// ---------------- scratch (no allocations allowed) ----------------
// g_hc[b][chunk][4096]: per 64-j chunk, tf32 (hi-only) interleaved:
//   float index = kt*512 + c*8 + q*2 + s,  s=0: h[j=8kt+q][c], s=1: h[j=8kt+q+4][c]
__device__ float g_hc[16 * 32 * 4096];    // 8.4 MB
__device__ float g_esrc[16 * 2048];       // exp(s_src)
__device__ float g_edst[16 * 2048];       // exp(s_dst)

// ---------------- helpers ----------------
__device__ __forceinline__ uint smem_u32(const void* p) {
    uint a;
    asm("{ .reg .u64 t; cvta.to.shared.u64 t, %1; cvt.u32.u64 %0, t; }" : "=r"(a) : "l"(p));
    return a;
}
__device__ __forceinline__ ull pack2(float lo, float hi) {
    ull r; asm("mov.b64 %0, {%1, %2};" : "=l"(r) : "f"(lo), "f"(hi)); return r;
}
__device__ __forceinline__ void unpack2(ull v, float& lo, float& hi) {
    asm("mov.b64 {%0, %1}, %2;" : "=f"(lo), "=f"(hi) : "l"(v));
}
__device__ __forceinline__ ull fma2(ull a, ull b, ull c) {
    ull d; asm("fma.rn.f32x2 %0, %1, %2, %3;" : "=l"(d) : "l"(a), "l"(b), "l"(c)); return d;
}
__device__ __forceinline__ float rna_tf32(float x) {
    float r; asm("cvt.rna.tf32.f32 %0, %1;" : "=f"(r) : "f"(x)); return r;
}
__device__ __forceinline__ void cpasync16(uint dst, const void* src) {
    asm volatile("cp.async.cg.shared.global [%0], [%1], 16;" :: "r"(dst), "l"(src));
}

// m16n8k8 tf32 mma, D/C fp32 (target-neutral PTX, works at sm_103)
#define MMA_TF32(d, A0, A1, A2, A3, B0, B1)                                   \
    asm volatile("mma.sync.aligned.m16n8k8.row.col.f32.tf32.tf32.f32 "        \
        "{%0,%1,%2,%3}, {%4,%5,%6,%7}, {%8,%9}, {%0,%1,%2,%3};"               \
        : "+f"((d)[0]), "+f"((d)[1]), "+f"((d)[2]), "+f"((d)[3])              \
        : "r"(A0), "r"(A1), "r"(A2), "r"(A3), "r"(B0), "r"(B1))

// ================================================================
// Kernel A: persistent gemm. 296 CTAs; W (64KB) loaded ONCE per CTA,
// then loop over 32-row tiles (cp.async-staged x). Emits g_hc
// (chunk-interleaved tf32 hi-only), g_esrc/g_edst = exp(s_src/dst).
// smem: ws 64KB + xs 32KB = 96KB -> 2 CTA/SM.
// ================================================================
__global__ void __launch_bounds__(256, 2) gemm_h_kernel(const float* __restrict__ x,
                                                        const float* __restrict__ W,
                                                        const float* __restrict__ w2) {
    extern __shared__ float dynsm[];
    float* ws = dynsm;            // [256][64]  = 64KB (persists all tiles)
    float* xs = dynsm + 16384;    // [32][256]  = 32KB (re-staged per tile)
    float* h_sm = xs;             // transpose staging overlays xs (32x65)

    const int t    = threadIdx.x;
    const int rowg = t >> 4;      // 0..15 -> 2 rows each
    const int cg   = t & 15;      // 4 cols
    const uint xs_u = smem_u32(xs);

    // load W once
    {
        const float4* wg  = (const float4*)W;
        float4*       ws4 = (float4*)ws;
        #pragma unroll
        for (int i = 0; i < 16; i++) ws4[t + i * 256] = wg[t + i * 256];
    }
    const float4 as = *(const float4*)(w2 + cg * 4);
    const float4 ad = *(const float4*)(w2 + 64 + cg * 4);
    __syncthreads();

    for (int tile = blockIdx.x; tile < 1024; tile += gridDim.x) {
        const long base_row = (long)tile * 32;

        // stage x tile: 32x256 f32 = 8192 floats = 2048 16B segments.
        // (Round-13 bug: it<2 staged only 512 segments -> rows 8..31 garbage.)
        #pragma unroll
        for (int it = 0; it < 8; it++) {
            const int s = t + it * 256;
            cpasync16(xs_u + (uint)s * 16, x + base_row * 256 + s * 4);
        }
        asm volatile("cp.async.commit_group;" ::: "memory");
        asm volatile("cp.async.wait_group 0;" ::: "memory");
        __syncthreads();

        ull acc2[2][2];
        #pragma unroll
        for (int r = 0; r < 2; r++) { acc2[r][0] = 0ULL; acc2[r][1] = 0ULL; }

        #pragma unroll 8
        for (int k = 0; k < 256; k++) {
            const ulonglong2 wv = *(const ulonglong2*)&ws[k * 64 + cg * 4];
            #pragma unroll
            for (int r = 0; r < 2; r++) {
                const float xv = xs[(rowg * 2 + r) * 256 + k];
                const ull x2 = pack2(xv, xv);
                acc2[r][0] = fma2(wv.x, x2, acc2[r][0]);
                acc2[r][1] = fma2(wv.y, x2, acc2[r][1]);
            }
        }

        float av[2][4];
        #pragma unroll
        for (int r = 0; r < 2; r++) {
            unpack2(acc2[r][0], av[r][0], av[r][1]);
            unpack2(acc2[r][1], av[r][2], av[r][3]);
            float ps = av[r][0] * as.x + av[r][1] * as.y + av[r][2] * as.z + av[r][3] * as.w;
            float pd = av[r][0] * ad.x + av[r][1] * ad.y + av[r][2] * ad.z + av[r][3] * ad.w;
            #pragma unroll
            for (int o = 1; o < 16; o <<= 1) {
                ps += __shfl_xor_sync(0xffffffffu, ps, o);
                pd += __shfl_xor_sync(0xffffffffu, pd, o);
            }
            if (cg == 0) {
                g_esrc[base_row + rowg * 2 + r] = __expf(ps);
                g_edst[base_row + rowg * 2 + r] = __expf(pd);
            }
        }

        // transpose via smem (overlays xs; k-loop readers must be done)
        __syncthreads();
        #pragma unroll
        for (int r = 0; r < 2; r++)
            #pragma unroll
            for (int u = 0; u < 4; u++)
                h_sm[(rowg * 2 + r) * 65 + cg * 4 + u] = av[r][u];
        __syncthreads();

        const int b     = (int)(base_row >> 11);
        const int ck    = (int)((base_row & 2047) >> 6);
        const int jhalf = (int)((base_row >> 5) & 1);
        float* dst = g_hc + ((long)b * 32 + ck) * 4096;
        #pragma unroll
        for (int it = 0; it < 4; it++) {
            const int f2l = t + it * 256;        // 0..1023
            const int ktl = f2l >> 8;
            const int c   = (f2l >> 2) & 63;
            const int q   = f2l & 3;
            const int jl  = ktl * 8 + q;
            const float hA = h_sm[jl * 65 + c];
            const float hB = h_sm[(jl + 4) * 65 + c];
            const int fi = (jhalf * 4 + ktl) * 512 + c * 8 + q * 2;
            *(float2*)(dst + fi) = make_float2(rna_tf32(hA), rna_tf32(hB));
        }
        __syncthreads();   // transpose readers done before next tile's xs write
    }
}

// ================================================================
// Kernel B: masked softmax + P@V, fragment-direct scores.
// CTA = 128 rows, 256 threads, 8 warps x 16 rows; 2 CTAs/SM.
// No psm: mma lane (q, r4) computes its 4 A-fragment p values per kt
// directly from adj (smem, rotation-swizzled: phys col = (c+4*row)&63,
// conflict-free across all 32 lanes) and e_src*e_dst:
//     p~ = adj>0 ? tf32(max(esrc*edst, 1)) : 0
// l summed in registers from the same p~ (q-lane shfl at end).
// adj double-buffered (2x32KB) + H hi-only double-buffered (2x16KB)
// via cp.async; e_dst row staged once (8KB). smem = 104KB.
// ================================================================
__global__ void __launch_bounds__(256, 2) attn_kernel(const int* __restrict__ adj,
                                                      float* __restrict__ out) {
    extern __shared__ float sm[];
    float* hs      = sm;                        // [2][4096]  32768B
    int*   adj_sm  = (int*)(sm + 8192);         // [2][8192]  65536B
    float* edst_sm = (float*)(adj_sm + 16384);  // [2048]     8192B

    const int t  = threadIdx.x;
    const int ln = t & 31;
    const int w  = t >> 5;
    const int b  = blockIdx.y;
    const int ib = blockIdx.x * 128;
    const long bn = (long)b * 2048;
    const int R0 = w * 16;

    const int q    = ln & 3;
    const int r4   = ln >> 2;
    const int row0 = R0 + r4;        // CTA-local rows this lane owns
    const int row1 = row0 + 8;

    const float es0 = g_esrc[bn + ib + row0];
    const float es1 = g_esrc[bn + ib + row1];

    const int*    adjg  = adj + (bn + ib) * 2048;
    const float4* hsrc4 = (const float4*)(g_hc + (long)b * 32 * 4096);
    const uint    hs_u   = smem_u32(hs);
    const uint    adj_u  = smem_u32(adj_sm);
    const uint    edst_u = smem_u32(edst_sm);

    float acc[8][4];
    #pragma unroll
    for (int nt = 0; nt < 8; nt++)
        #pragma unroll
        for (int e = 0; e < 4; e++) acc[nt][e] = 0.f;
    float l0 = 0.f, l1 = 0.f;

    // prologue: e_dst (whole batch row, 512 segs), adj[0], H[0]
    #pragma unroll
    for (int it = 0; it < 2; it++) {
        const int s = t + it * 256;
        cpasync16(edst_u + (uint)s * 16, g_edst + bn + s * 4);
    }
    #pragma unroll
    for (int it = 0; it < 8; it++) {
        const int s = t + it * 256;              // 2048 segs: row, 16B-group g
        const int row = s >> 4, g = s & 15;
        cpasync16(adj_u + (uint)(row * 64 + ((g + row) & 15) * 4) * 4,
                  adjg + (long)row * 2048 + g * 4);
    }
    #pragma unroll
    for (int it = 0; it < 4; it++)
        cpasync16(hs_u + (uint)(t + it * 256) * 16, hsrc4 + t + it * 256);
    asm volatile("cp.async.commit_group;" ::: "memory");
    asm volatile("cp.async.wait_group 0;" ::: "memory");
    __syncthreads();

    for (int ck = 0; ck < 32; ck++) {
        const int buf = ck & 1;
        const int jc  = ck * 64;

        // ---- prefetch chunk ck+1 into the other buffers ----
        if (ck < 31) {
            #pragma unroll
            for (int it = 0; it < 8; it++) {
                const int s = t + it * 256;
                const int row = s >> 4, g = s & 15;
                cpasync16(adj_u + (uint)((buf ^ 1) * 8192 + row * 64 + ((g + row) & 15) * 4) * 4,
                          adjg + (long)row * 2048 + (jc + 64) + g * 4);
            }
            const float4* hsv = hsrc4 + (ck + 1) * 1024;
            #pragma unroll
            for (int it = 0; it < 4; it++)
                cpasync16(hs_u + (uint)(buf ^ 1) * 16384 + (uint)(t + it * 256) * 16,
                          hsv + t + it * 256);
            asm volatile("cp.async.commit_group;" ::: "memory");
        }

        // ---- fused score + mma ----
        const float* hb = hs + buf * 4096;
        const int*   ab = adj_sm + buf * 8192;
        #pragma unroll
        for (int kt = 0; kt < 8; kt++) {
            const int c0 = kt * 8 + q;
            const int c1 = c0 + 4;
            const int a00 = ab[row0 * 64 + ((c0 + 4 * row0) & 63)];
            const int a01 = ab[row0 * 64 + ((c1 + 4 * row0) & 63)];
            const int a10 = ab[row1 * 64 + ((c0 + 4 * row1) & 63)];
            const int a11 = ab[row1 * 64 + ((c1 + 4 * row1) & 63)];
            const float ed0 = edst_sm[jc + c0];
            const float ed1 = edst_sm[jc + c1];
            const float A0f = (a00 > 0) ? rna_tf32(fmaxf(es0 * ed0, 1.f)) : 0.f;
            const float A1f = (a10 > 0) ? rna_tf32(fmaxf(es1 * ed0, 1.f)) : 0.f;
            const float A2f = (a01 > 0) ? rna_tf32(fmaxf(es0 * ed1, 1.f)) : 0.f;
            const float A3f = (a11 > 0) ? rna_tf32(fmaxf(es1 * ed1, 1.f)) : 0.f;
            l0 += A0f + A2f;
            l1 += A1f + A3f;
            const uint A0 = __float_as_uint(A0f), A1 = __float_as_uint(A1f);
            const uint A2 = __float_as_uint(A2f), A3 = __float_as_uint(A3f);
            #pragma unroll
            for (int nt = 0; nt < 8; nt++) {
                const int c = nt * 8 + r4;
                const float2 bq = *(const float2*)&hb[kt * 512 + c * 8 + q * 2];
                MMA_TF32(acc[nt], A0, A1, A2, A3,
                         __float_as_uint(bq.x), __float_as_uint(bq.y));
            }
        }

        if (ck < 31) asm volatile("cp.async.wait_group 0;" ::: "memory");
        __syncthreads();
    }

    // ---- l: cols of each row partition over the 4 q-lanes ----
    l0 += __shfl_xor_sync(0xffffffffu, l0, 1);
    l0 += __shfl_xor_sync(0xffffffffu, l0, 2);
    l1 += __shfl_xor_sync(0xffffffffu, l1, 1);
    l1 += __shfl_xor_sync(0xffffffffu, l1, 2);
    const float inv0 = 1.f / l0;
    const float inv1 = 1.f / l1;

    // ---- epilogue ----
    const long rg = bn + ib + row0;
    #pragma unroll
    for (int nt = 0; nt < 8; nt++) {
        *(float2*)(out + rg * 64 + nt * 8 + 2 * q) =
            make_float2(acc[nt][0] * inv0, acc[nt][1] * inv0);
        *(float2*)(out + (rg + 8) * 64 + nt * 8 + 2 * q) =
            make_float2(acc[nt][2] * inv1, acc[nt][3] * inv1);
    }
}

// ================================================================
// launch
// inputs: x f32[16,2048,256], adj i32[16,2048,2048],
//         weight f32[256,64], weight2 f32[128,1]
// output: f32[16,2048,64]
// ================================================================
extern "C" void kernel_launch(void* const* d_in, const int* in_sizes, int n_in,
                              void* d_out, int out_size) {
    const float* x   = (const float*)d_in[0];
    const int*   adj = (const int*)d_in[1];
    const float* W   = (const float*)d_in[2];
    const float* w2  = (const float*)d_in[3];
    float* out = (float*)d_out;

    cudaFuncSetAttribute(gemm_h_kernel,
                         cudaFuncAttributeMaxDynamicSharedMemorySize, 98304);
    cudaFuncSetAttribute(attn_kernel,
                         cudaFuncAttributeMaxDynamicSharedMemorySize, 106496);

    gemm_h_kernel<<<296, 256, 98304>>>(x, W, w2);          // persistent, W once
    attn_kernel<<<dim3(16, 16), 256, 106496>>>(adj, out);  // 128 rows/CTA
}

// round 16
// speedup vs baseline: 2.6043x; 1.1469x over previous
#include <cuda_runtime.h>
#include <math.h>
#include <stdint.h>

typedef unsigned long long ull;
typedef unsigned int uint;

// ---------------- scratch (no allocations allowed) ----------------
// g_hc[b][chunk][4096]: per 64-j chunk, tf32 (hi-only) interleaved:
//   float index = kt*512 + c*8 + q*2 + s,  s=0: h[j=8kt+q][c], s=1: h[j=8kt+q+4][c]
__device__ float g_hc[16 * 32 * 4096];    // 8.4 MB
__device__ float g_esrc[16 * 2048];       // exp(s_src)
__device__ float g_edst[16 * 2048];       // exp(s_dst)

// ---------------- helpers ----------------
__device__ __forceinline__ uint smem_u32(const void* p) {
    uint a;
    asm("{ .reg .u64 t; cvta.to.shared.u64 t, %1; cvt.u32.u64 %0, t; }" : "=r"(a) : "l"(p));
    return a;
}
__device__ __forceinline__ float rna_tf32(float x) {
    float r; asm("cvt.rna.tf32.f32 %0, %1;" : "=f"(r) : "f"(x)); return r;
}
__device__ __forceinline__ void cpasync16(uint dst, const void* src) {
    asm volatile("cp.async.cg.shared.global [%0], [%1], 16;" :: "r"(dst), "l"(src));
}

// m16n8k8 tf32 mma, D/C fp32 (target-neutral PTX, works at sm_103)
#define MMA_TF32(d, A0, A1, A2, A3, B0, B1)                                   \
    asm volatile("mma.sync.aligned.m16n8k8.row.col.f32.tf32.tf32.f32 "        \
        "{%0,%1,%2,%3}, {%4,%5,%6,%7}, {%8,%9}, {%0,%1,%2,%3};"               \
        : "+f"((d)[0]), "+f"((d)[1]), "+f"((d)[2]), "+f"((d)[3])              \
        : "r"(A0), "r"(A1), "r"(A2), "r"(A3), "r"(B0), "r"(B1))

// ================================================================
// Kernel A: tensor-core gemm. Persistent 296 CTAs.
// Scores use the identity s_src = x·(W a_src): va/vb computed from
// EXACT fp32 W in the prologue, so scores (exp-amplified) stay fp32-
// exact while h itself runs on tf32 mma (h only feeds linear P@V).
// Prologue: stage W fp32 (stride 72) -> va/vb -> cvt W to tf32 in place.
// Per 32-row tile: cp.async x (fp32, stride 260) -> exact scores ->
// 32kt x 2nt m16n8k8 per warp -> D frags -> smem -> g_hc emission.
// smem: ws 73728 + xs 33280 + va/vb 2048 = 109056B -> 2 CTA/SM.
// ================================================================
__global__ void __launch_bounds__(256, 2) gemm_h_kernel(const float* __restrict__ x,
                                                        const float* __restrict__ W,
                                                        const float* __restrict__ w2) {
    extern __shared__ float dynsm[];
    float* ws = dynsm;              // [256][72] W: fp32 then tf32 in place
    float* xs = dynsm + 18432;      // [32][260] x tile, fp32 exact
    float* va = dynsm + 26752;      // [256] = W @ a_src (exact fp32)
    float* vb = dynsm + 27008;      // [256] = W @ a_dst

    const int t  = threadIdx.x;
    const int ln = t & 31;
    const int w  = t >> 5;
    const int q  = ln & 3;
    const int r4 = ln >> 2;
    const int rt = w >> 2;          // row-tile (0..1) -> rows rt*16..+16
    const int ng = w & 3;           // col-group -> cols ng*16..+16
    const int rbase = rt * 16;
    const int nb    = ng * 16;
    const uint ws_u = smem_u32(ws);
    const uint xs_u = smem_u32(xs);

    // ---- prologue: stage W fp32.
    // W = 256x64 f32 = 4096 16B segments -> it < 16.
    // (Round-15 bug: it<4 staged only k-rows 0..63; rows 64..255 garbage.)
    #pragma unroll
    for (int it = 0; it < 16; it++) {
        const int s = t + it * 256;          // 0..4095
        const int k = s >> 4, g = s & 15;
        cpasync16(ws_u + (uint)(k * 288 + g * 16), W + k * 64 + g * 4);
    }
    asm volatile("cp.async.commit_group;" ::: "memory");
    asm volatile("cp.async.wait_group 0;" ::: "memory");
    __syncthreads();

    // va/vb from EXACT fp32 W (thread t owns k = t)
    {
        float sa = 0.f, sb = 0.f;
        #pragma unroll 8
        for (int n = 0; n < 64; n++) {
            const float wv = ws[t * 72 + n];
            sa += wv * __ldg(w2 + n);
            sb += wv * __ldg(w2 + 64 + n);
        }
        va[t] = sa;
        vb[t] = sb;
    }
    __syncthreads();

    // cvt W to tf32 in place
    #pragma unroll
    for (int g = 0; g < 16; g++) {
        float4 v = *(float4*)&ws[t * 72 + g * 4];
        v.x = rna_tf32(v.x); v.y = rna_tf32(v.y);
        v.z = rna_tf32(v.z); v.w = rna_tf32(v.w);
        *(float4*)&ws[t * 72 + g * 4] = v;
    }
    __syncthreads();

    // ---- tile loop ----
    for (int tile = blockIdx.x; tile < 1024; tile += 296) {
        const long base_row = (long)tile * 32;

        // stage x: 32 rows x 256 f32 = 2048 segs of 16B (row stride 260)
        #pragma unroll
        for (int it = 0; it < 8; it++) {
            const int s = t + it * 256;
            const int row = s >> 6, g = s & 63;
            cpasync16(xs_u + (uint)(row * 1040 + g * 16),
                      x + base_row * 256 + row * 256 + g * 4);
        }
        asm volatile("cp.async.commit_group;" ::: "memory");
        asm volatile("cp.async.wait_group 0;" ::: "memory");
        __syncthreads();

        // exact fp32 scores: 8 threads per row, 32 k's each (lane-rotated)
        {
            const int row_s = t >> 3;
            const int ko    = (t & 7) * 32;
            const int rot   = (t & 7) * 4;
            float ss = 0.f, sd = 0.f;
            #pragma unroll 8
            for (int i = 0; i < 32; i++) {
                const int kk = ko + ((i + rot) & 31);
                const float xv = xs[row_s * 260 + kk];
                ss += xv * va[kk];
                sd += xv * vb[kk];
            }
            ss += __shfl_xor_sync(0xffffffffu, ss, 1);
            sd += __shfl_xor_sync(0xffffffffu, sd, 1);
            ss += __shfl_xor_sync(0xffffffffu, ss, 2);
            sd += __shfl_xor_sync(0xffffffffu, sd, 2);
            ss += __shfl_xor_sync(0xffffffffu, ss, 4);
            sd += __shfl_xor_sync(0xffffffffu, sd, 4);
            if ((t & 7) == 0) {
                g_esrc[base_row + row_s] = __expf(ss);
                g_edst[base_row + row_s] = __expf(sd);
            }
        }

        // mma: h-tile rows rbase..+16, cols nb..+16, K = 256 (32 kt)
        float acc[2][4];
        #pragma unroll
        for (int nt = 0; nt < 2; nt++)
            #pragma unroll
            for (int e = 0; e < 4; e++) acc[nt][e] = 0.f;

        #pragma unroll 4
        for (int kt = 0; kt < 32; kt++) {
            const int k0 = kt * 8 + q;
            const uint A0 = __float_as_uint(rna_tf32(xs[(rbase + r4) * 260 + k0]));
            const uint A1 = __float_as_uint(rna_tf32(xs[(rbase + r4 + 8) * 260 + k0]));
            const uint A2 = __float_as_uint(rna_tf32(xs[(rbase + r4) * 260 + k0 + 4]));
            const uint A3 = __float_as_uint(rna_tf32(xs[(rbase + r4 + 8) * 260 + k0 + 4]));
            #pragma unroll
            for (int nt = 0; nt < 2; nt++) {
                const int n = nb + nt * 8 + r4;
                const uint b0 = __float_as_uint(ws[k0 * 72 + n]);
                const uint b1 = __float_as_uint(ws[(k0 + 4) * 72 + n]);
                MMA_TF32(acc[nt], A0, A1, A2, A3, b0, b1);
            }
        }
        __syncthreads();   // all xs readers (scores + mma) done

        // D fragments -> h_sm (overlays xs, stride 72)
        float* h_sm = xs;
        #pragma unroll
        for (int nt = 0; nt < 2; nt++) {
            const int c = nb + nt * 8 + 2 * q;
            *(float2*)&h_sm[(rbase + r4) * 72 + c]     = make_float2(acc[nt][0], acc[nt][1]);
            *(float2*)&h_sm[(rbase + r4 + 8) * 72 + c] = make_float2(acc[nt][2], acc[nt][3]);
        }
        __syncthreads();

        // emission to g_hc (chunk-interleaved tf32), stride-72 source
        const int b     = (int)(base_row >> 11);
        const int ck    = (int)((base_row & 2047) >> 6);
        const int jhalf = (int)((base_row >> 5) & 1);
        float* dst = g_hc + ((long)b * 32 + ck) * 4096;
        #pragma unroll
        for (int it = 0; it < 4; it++) {
            const int f2l = t + it * 256;        // 0..1023
            const int ktl = f2l >> 8;
            const int c   = (f2l >> 2) & 63;
            const int qq  = f2l & 3;
            const int jl  = ktl * 8 + qq;
            const float hA = h_sm[jl * 72 + c];
            const float hB = h_sm[(jl + 4) * 72 + c];
            const int fi = (jhalf * 4 + ktl) * 512 + c * 8 + qq * 2;
            *(float2*)(dst + fi) = make_float2(rna_tf32(hA), rna_tf32(hB));
        }
        __syncthreads();   // emission readers done before next tile's xs write
    }
}

// ================================================================
// Kernel B: masked softmax + P@V, fragment-direct scores.
// (unchanged from Round 14 — proven at 89.4us / rel_err 2.05e-4)
// ================================================================
__global__ void __launch_bounds__(256, 2) attn_kernel(const int* __restrict__ adj,
                                                      float* __restrict__ out) {
    extern __shared__ float sm[];
    float* hs      = sm;                        // [2][4096]  32768B
    int*   adj_sm  = (int*)(sm + 8192);         // [2][8192]  65536B
    float* edst_sm = (float*)(adj_sm + 16384);  // [2048]     8192B

    const int t  = threadIdx.x;
    const int ln = t & 31;
    const int w  = t >> 5;
    const int b  = blockIdx.y;
    const int ib = blockIdx.x * 128;
    const long bn = (long)b * 2048;
    const int R0 = w * 16;

    const int q    = ln & 3;
    const int r4   = ln >> 2;
    const int row0 = R0 + r4;
    const int row1 = row0 + 8;

    const float es0 = g_esrc[bn + ib + row0];
    const float es1 = g_esrc[bn + ib + row1];

    const int*    adjg  = adj + (bn + ib) * 2048;
    const float4* hsrc4 = (const float4*)(g_hc + (long)b * 32 * 4096);
    const uint    hs_u   = smem_u32(hs);
    const uint    adj_u  = smem_u32(adj_sm);
    const uint    edst_u = smem_u32(edst_sm);

    float acc[8][4];
    #pragma unroll
    for (int nt = 0; nt < 8; nt++)
        #pragma unroll
        for (int e = 0; e < 4; e++) acc[nt][e] = 0.f;
    float l0 = 0.f, l1 = 0.f;

    // prologue: e_dst (whole batch row), adj[0], H[0]
    #pragma unroll
    for (int it = 0; it < 2; it++) {
        const int s = t + it * 256;
        cpasync16(edst_u + (uint)s * 16, g_edst + bn + s * 4);
    }
    #pragma unroll
    for (int it = 0; it < 8; it++) {
        const int s = t + it * 256;
        const int row = s >> 4, g = s & 15;
        cpasync16(adj_u + (uint)(row * 64 + ((g + row) & 15) * 4) * 4,
                  adjg + (long)row * 2048 + g * 4);
    }
    #pragma unroll
    for (int it = 0; it < 4; it++)
        cpasync16(hs_u + (uint)(t + it * 256) * 16, hsrc4 + t + it * 256);
    asm volatile("cp.async.commit_group;" ::: "memory");
    asm volatile("cp.async.wait_group 0;" ::: "memory");
    __syncthreads();

    for (int ck = 0; ck < 32; ck++) {
        const int buf = ck & 1;
        const int jc  = ck * 64;

        // prefetch chunk ck+1 into the other buffers
        if (ck < 31) {
            #pragma unroll
            for (int it = 0; it < 8; it++) {
                const int s = t + it * 256;
                const int row = s >> 4, g = s & 15;
                cpasync16(adj_u + (uint)((buf ^ 1) * 8192 + row * 64 + ((g + row) & 15) * 4) * 4,
                          adjg + (long)row * 2048 + (jc + 64) + g * 4);
            }
            const float4* hsv = hsrc4 + (ck + 1) * 1024;
            #pragma unroll
            for (int it = 0; it < 4; it++)
                cpasync16(hs_u + (uint)(buf ^ 1) * 16384 + (uint)(t + it * 256) * 16,
                          hsv + t + it * 256);
            asm volatile("cp.async.commit_group;" ::: "memory");
        }

        // fused score + mma
        const float* hb = hs + buf * 4096;
        const int*   ab = adj_sm + buf * 8192;
        #pragma unroll
        for (int kt = 0; kt < 8; kt++) {
            const int c0 = kt * 8 + q;
            const int c1 = c0 + 4;
            const int a00 = ab[row0 * 64 + ((c0 + 4 * row0) & 63)];
            const int a01 = ab[row0 * 64 + ((c1 + 4 * row0) & 63)];
            const int a10 = ab[row1 * 64 + ((c0 + 4 * row1) & 63)];
            const int a11 = ab[row1 * 64 + ((c1 + 4 * row1) & 63)];
            const float ed0 = edst_sm[jc + c0];
            const float ed1 = edst_sm[jc + c1];
            const float A0f = (a00 > 0) ? rna_tf32(fmaxf(es0 * ed0, 1.f)) : 0.f;
            const float A1f = (a10 > 0) ? rna_tf32(fmaxf(es1 * ed0, 1.f)) : 0.f;
            const float A2f = (a01 > 0) ? rna_tf32(fmaxf(es0 * ed1, 1.f)) : 0.f;
            const float A3f = (a11 > 0) ? rna_tf32(fmaxf(es1 * ed1, 1.f)) : 0.f;
            l0 += A0f + A2f;
            l1 += A1f + A3f;
            const uint A0 = __float_as_uint(A0f), A1 = __float_as_uint(A1f);
            const uint A2 = __float_as_uint(A2f), A3 = __float_as_uint(A3f);
            #pragma unroll
            for (int nt = 0; nt < 8; nt++) {
                const int c = nt * 8 + r4;
                const float2 bq = *(const float2*)&hb[kt * 512 + c * 8 + q * 2];
                MMA_TF32(acc[nt], A0, A1, A2, A3,
                         __float_as_uint(bq.x), __float_as_uint(bq.y));
            }
        }

        if (ck < 31) asm volatile("cp.async.wait_group 0;" ::: "memory");
        __syncthreads();
    }

    // l: each row's cols partition over the 4 q-lanes
    l0 += __shfl_xor_sync(0xffffffffu, l0, 1);
    l0 += __shfl_xor_sync(0xffffffffu, l0, 2);
    l1 += __shfl_xor_sync(0xffffffffu, l1, 1);
    l1 += __shfl_xor_sync(0xffffffffu, l1, 2);
    const float inv0 = 1.f / l0;
    const float inv1 = 1.f / l1;

    // epilogue
    const long rg = bn + ib + row0;
    #pragma unroll
    for (int nt = 0; nt < 8; nt++) {
        *(float2*)(out + rg * 64 + nt * 8 + 2 * q) =
            make_float2(acc[nt][0] * inv0, acc[nt][1] * inv0);
        *(float2*)(out + (rg + 8) * 64 + nt * 8 + 2 * q) =
            make_float2(acc[nt][2] * inv1, acc[nt][3] * inv1);
    }
}

// ================================================================
// launch
// inputs: x f32[16,2048,256], adj i32[16,2048,2048],
//         weight f32[256,64], weight2 f32[128,1]
// output: f32[16,2048,64]
// ================================================================
extern "C" void kernel_launch(void* const* d_in, const int* in_sizes, int n_in,
                              void* d_out, int out_size) {
    const float* x   = (const float*)d_in[0];
    const int*   adj = (const int*)d_in[1];
    const float* W   = (const float*)d_in[2];
    const float* w2  = (const float*)d_in[3];
    float* out = (float*)d_out;

    cudaFuncSetAttribute(gemm_h_kernel,
                         cudaFuncAttributeMaxDynamicSharedMemorySize, 109056);
    cudaFuncSetAttribute(attn_kernel,
                         cudaFuncAttributeMaxDynamicSharedMemorySize, 106496);

    gemm_h_kernel<<<296, 256, 109056>>>(x, W, w2);         // persistent mma gemm
    attn_kernel<<<dim3(16, 16), 256, 106496>>>(adj, out);  // 128 rows/CTA
}

// round 17
// speedup vs baseline: 2.6918x; 1.0336x over previous
#include <cuda_runtime.h>
#include <math.h>
#include <stdint.h>

typedef unsigned long long ull;
typedef unsigned int uint;

// ---------------- scratch (no allocations allowed) ----------------
// g_hc[b][chunk][4096]: per 64-j chunk, tf32, B-frag-quad layout:
//   word index = kt*512 + ((rc>>1)*8 + q*2 + (rc&1))*4 + p*128 + hbit*2 + e
//   holds, for e=0..1 at hbit: h[8kt+q + 4e][16p + 8hbit + rc]
//   (one 16B quad = both n-halves of an nt-pair for lane (q,rc))
__device__ float g_hc[16 * 32 * 4096];    // 8.4 MB
__device__ float g_esrc[16 * 2048];       // exp(s_src)
__device__ float g_edst[16 * 2048];       // exp(s_dst)

// ---------------- helpers ----------------
__device__ __forceinline__ uint smem_u32(const void* p) {
    uint a;
    asm("{ .reg .u64 t; cvta.to.shared.u64 t, %1; cvt.u32.u64 %0, t; }" : "=r"(a) : "l"(p));
    return a;
}
__device__ __forceinline__ float rna_tf32(float x) {
    float r; asm("cvt.rna.tf32.f32 %0, %1;" : "=f"(r) : "f"(x)); return r;
}
__device__ __forceinline__ void cpasync16(uint dst, const void* src) {
    asm volatile("cp.async.cg.shared.global [%0], [%1], 16;" :: "r"(dst), "l"(src));
}

// m16n8k8 tf32 mma, D/C fp32 (target-neutral PTX, works at sm_103)
#define MMA_TF32(d, A0, A1, A2, A3, B0, B1)                                   \
    asm volatile("mma.sync.aligned.m16n8k8.row.col.f32.tf32.tf32.f32 "        \
        "{%0,%1,%2,%3}, {%4,%5,%6,%7}, {%8,%9}, {%0,%1,%2,%3};"               \
        : "+f"((d)[0]), "+f"((d)[1]), "+f"((d)[2]), "+f"((d)[3])              \
        : "r"(A0), "r"(A1), "r"(A2), "r"(A3), "r"(B0), "r"(B1))

// ================================================================
// Kernel A: tensor-core gemm. Persistent 296 CTAs, 16-row tiles,
// DOUBLE-BUFFERED x staging (prefetch tile i+1 under tile i compute).
// Scores: s_src = x·(W a_src) with va/vb from EXACT fp32 W (scores
// stay fp32-exact); h runs on tf32 mma (linear path only).
// smem: ws[256][68] 69632 + xs 2x16640 + h_sm[16][68] 4352 +
//       va/vb 2048 = 109312B -> 2 CTA/SM.
// ================================================================
__global__ void __launch_bounds__(256, 2) gemm_h_kernel(const float* __restrict__ x,
                                                        const float* __restrict__ W,
                                                        const float* __restrict__ w2) {
    extern __shared__ float dynsm[];
    float* ws   = dynsm;              // [256][68] W: fp32 then tf32 in place
    float* xs   = dynsm + 17408;      // 2 x [16][260]
    float* h_sm = dynsm + 25728;      // [16][68]
    float* va   = dynsm + 26816;      // [256]
    float* vb   = dynsm + 27072;      // [256]

    const int t  = threadIdx.x;
    const int ln = t & 31;
    const int w  = t >> 5;            // warp -> n-group w*8..+8
    const int q  = ln & 3;
    const int r4 = ln >> 2;
    const uint ws_u = smem_u32(ws);
    const uint xs_u = smem_u32(xs);

    // ---- prologue: stage W fp32 (256x64 = 4096 16B segs) ----
    #pragma unroll
    for (int it = 0; it < 16; it++) {
        const int s = t + it * 256;
        const int k = s >> 4, g = s & 15;
        cpasync16(ws_u + (uint)(k * 272 + g * 16), W + k * 64 + g * 4);
    }
    asm volatile("cp.async.commit_group;" ::: "memory");
    asm volatile("cp.async.wait_group 0;" ::: "memory");
    __syncthreads();

    // va/vb from EXACT fp32 W (thread t owns k = t)
    {
        float sa = 0.f, sb = 0.f;
        #pragma unroll 8
        for (int n = 0; n < 64; n++) {
            const float wv = ws[t * 68 + n];
            sa += wv * __ldg(w2 + n);
            sb += wv * __ldg(w2 + 64 + n);
        }
        va[t] = sa;
        vb[t] = sb;
    }
    __syncthreads();

    // cvt W to tf32 in place
    #pragma unroll
    for (int g = 0; g < 16; g++) {
        float4 v = *(float4*)&ws[t * 68 + g * 4];
        v.x = rna_tf32(v.x); v.y = rna_tf32(v.y);
        v.z = rna_tf32(v.z); v.w = rna_tf32(v.w);
        *(float4*)&ws[t * 68 + g * 4] = v;
    }
    __syncthreads();

    // ---- stage first tile into xs[0] (16x256 = 1024 16B segs) ----
    const int tile0 = blockIdx.x;
    {
        const float* src = x + (long)tile0 * 16 * 256;
        #pragma unroll
        for (int it = 0; it < 4; it++) {
            const int s = t + it * 256;
            const int row = s >> 6, g = s & 63;
            cpasync16(xs_u + (uint)(row * 1040 + g * 16), src + row * 256 + g * 4);
        }
        asm volatile("cp.async.commit_group;" ::: "memory");
    }

    int pb = 0;
    for (int tile = tile0; tile < 2048; tile += 296) {
        const int buf = pb; pb ^= 1;
        const long base_row = (long)tile * 16;

        asm volatile("cp.async.wait_group 0;" ::: "memory");
        __syncthreads();                  // xs[buf] ready; prev h_sm readers done

        // prefetch next tile into xs[buf^1]
        if (tile + 296 < 2048) {
            const float* src = x + (long)(tile + 296) * 16 * 256;
            const uint d = xs_u + (uint)(buf ^ 1) * 16640;
            #pragma unroll
            for (int it = 0; it < 4; it++) {
                const int s = t + it * 256;
                const int row = s >> 6, g = s & 63;
                cpasync16(d + (uint)(row * 1040 + g * 16), src + row * 256 + g * 4);
            }
            asm volatile("cp.async.commit_group;" ::: "memory");
        }

        const float* xb = xs + buf * 4160;

        // ---- exact fp32 scores: 16 threads/row, 16 k's each ----
        {
            const int row_s = t >> 4;
            const int c16   = t & 15;
            const int ko    = c16 * 16;
            float ss = 0.f, sd = 0.f;
            #pragma unroll 8
            for (int i = 0; i < 16; i++) {
                const int kk = ko + ((i + c16) & 15);
                const float xv = xb[row_s * 260 + kk];
                ss += xv * va[kk];
                sd += xv * vb[kk];
            }
            #pragma unroll
            for (int o = 1; o < 16; o <<= 1) {
                ss += __shfl_xor_sync(0xffffffffu, ss, o);
                sd += __shfl_xor_sync(0xffffffffu, sd, o);
            }
            if (c16 == 0) {
                g_esrc[base_row + row_s] = __expf(ss);
                g_edst[base_row + row_s] = __expf(sd);
            }
        }

        // ---- mma: 16 rows x 64 cols, warp w owns cols w*8..+8 ----
        float acc[4] = {0.f, 0.f, 0.f, 0.f};
        const int n = w * 8 + r4;
        #pragma unroll 8
        for (int kt = 0; kt < 32; kt++) {
            const int k0 = kt * 8 + q;
            const uint A0 = __float_as_uint(rna_tf32(xb[r4 * 260 + k0]));
            const uint A1 = __float_as_uint(rna_tf32(xb[(r4 + 8) * 260 + k0]));
            const uint A2 = __float_as_uint(rna_tf32(xb[r4 * 260 + k0 + 4]));
            const uint A3 = __float_as_uint(rna_tf32(xb[(r4 + 8) * 260 + k0 + 4]));
            const uint b0 = __float_as_uint(ws[k0 * 68 + n]);
            const uint b1 = __float_as_uint(ws[(k0 + 4) * 68 + n]);
            MMA_TF32(acc, A0, A1, A2, A3, b0, b1);
        }

        // D fragments -> h_sm
        *(float2*)&h_sm[r4 * 68 + w * 8 + 2 * q]       = make_float2(acc[0], acc[1]);
        *(float2*)&h_sm[(r4 + 8) * 68 + w * 8 + 2 * q] = make_float2(acc[2], acc[3]);
        __syncthreads();

        // ---- emission to g_hc (B-frag-quad layout), 512 float2 ----
        const int b   = (int)(base_row >> 11);
        const int ck  = (int)((base_row & 2047) >> 6);
        const int jq  = (int)((base_row >> 4) & 3);
        float* dst = g_hc + ((long)b * 32 + ck) * 4096;
        #pragma unroll
        for (int e2 = 0; e2 < 2; e2++) {
            const int idx  = t + e2 * 256;        // 0..511
            const int jsel = idx >> 6;            // 0..7
            const int ktl  = jsel >> 2;
            const int qj   = jsel & 3;
            const int jl   = ktl * 8 + qj;
            const int c    = idx & 63;
            const float hA = h_sm[jl * 68 + c];
            const float hB = h_sm[(jl + 4) * 68 + c];
            const int rc   = c & 7;
            const int hbit = (c >> 3) & 1;
            const int p    = c >> 4;
            const int ktg  = jq * 2 + ktl;
            const int off  = ktg * 512 + ((rc >> 1) * 8 + qj * 2 + (rc & 1)) * 4
                           + p * 128 + hbit * 2;
            *(float2*)(dst + off) = make_float2(rna_tf32(hA), rna_tf32(hB));
        }
        // no trailing barrier: next iteration's top barrier orders
        // h_sm reuse; xs[buf] is not rewritten until iteration i+2's
        // prefetch, which is after iteration i+1's top barrier.
    }
}

// ================================================================
// Kernel B: masked softmax + P@V, fragment-direct scores.
// CTA = 128 rows, 256 threads, 8 warps x 16 rows; 2 CTAs/SM.
// p~ = adj>0 ? tf32(max(esrc*edst, 1)) : 0  (exp-free; l from same p~).
// adj XOR-swizzled in smem (phys word = c ^ 4*(row&15); operand = 4*r4
// per lane), double-buffered 2x32KB. H in B-frag-quad layout: one
// LDS.128 feeds TWO MMAs (nt-pair). hs double-buffered 2x16KB.
// ================================================================
__global__ void __launch_bounds__(256, 2) attn_kernel(const int* __restrict__ adj,
                                                      float* __restrict__ out) {
    extern __shared__ float sm[];
    float* hs      = sm;                        // [2][4096]  32768B
    int*   adj_sm  = (int*)(sm + 8192);         // [2][8192]  65536B
    float* edst_sm = (float*)(adj_sm + 16384);  // [2048]     8192B

    const int t  = threadIdx.x;
    const int ln = t & 31;
    const int w  = t >> 5;
    const int b  = blockIdx.y;
    const int ib = blockIdx.x * 128;
    const long bn = (long)b * 2048;
    const int R0 = w * 16;

    const int q    = ln & 3;
    const int r4   = ln >> 2;
    const int row0 = R0 + r4;
    const int row1 = row0 + 8;
    const int xr0  = r4 * 4;                    // XOR operand (row0&15 == r4)
    const int hoff = ((r4 >> 1) * 8 + q * 2 + (r4 & 1)) * 4;

    const float es0 = g_esrc[bn + ib + row0];
    const float es1 = g_esrc[bn + ib + row1];

    const int*    adjg  = adj + (bn + ib) * 2048;
    const float4* hsrc4 = (const float4*)(g_hc + (long)b * 32 * 4096);
    const uint    hs_u   = smem_u32(hs);
    const uint    adj_u  = smem_u32(adj_sm);
    const uint    edst_u = smem_u32(edst_sm);

    float acc[8][4];
    #pragma unroll
    for (int nt = 0; nt < 8; nt++)
        #pragma unroll
        for (int e = 0; e < 4; e++) acc[nt][e] = 0.f;
    float l0 = 0.f, l1 = 0.f;

    // prologue: e_dst (whole batch row), adj[0] (XOR swizzle), H[0]
    #pragma unroll
    for (int it = 0; it < 2; it++) {
        const int s = t + it * 256;
        cpasync16(edst_u + (uint)s * 16, g_edst + bn + s * 4);
    }
    #pragma unroll
    for (int it = 0; it < 8; it++) {
        const int s = t + it * 256;              // 2048 segs
        const int row = s >> 4, g = s & 15;
        cpasync16(adj_u + (uint)(row * 16 + (g ^ (row & 15))) * 16,
                  adjg + (long)row * 2048 + g * 4);
    }
    #pragma unroll
    for (int it = 0; it < 4; it++)
        cpasync16(hs_u + (uint)(t + it * 256) * 16, hsrc4 + t + it * 256);
    asm volatile("cp.async.commit_group;" ::: "memory");
    asm volatile("cp.async.wait_group 0;" ::: "memory");
    __syncthreads();

    for (int ck = 0; ck < 32; ck++) {
        const int buf = ck & 1;
        const int jc  = ck * 64;

        // prefetch chunk ck+1 into the other buffers
        if (ck < 31) {
            #pragma unroll
            for (int it = 0; it < 8; it++) {
                const int s = t + it * 256;
                const int row = s >> 4, g = s & 15;
                cpasync16(adj_u + (uint)((buf ^ 1) * 2048 + row * 16 + (g ^ (row & 15))) * 16,
                          adjg + (long)row * 2048 + (jc + 64) + g * 4);
            }
            const float4* hsv = hsrc4 + (ck + 1) * 1024;
            #pragma unroll
            for (int it = 0; it < 4; it++)
                cpasync16(hs_u + (uint)(buf ^ 1) * 16384 + (uint)(t + it * 256) * 16,
                          hsv + t + it * 256);
            asm volatile("cp.async.commit_group;" ::: "memory");
        }

        // fused score + mma
        const float* hb  = hs + buf * 4096;
        const int*   ab0 = adj_sm + buf * 8192 + row0 * 64;
        const int*   ab1 = adj_sm + buf * 8192 + row1 * 64;
        #pragma unroll
        for (int kt = 0; kt < 8; kt++) {
            const int w0 = (kt * 8 + q) ^ xr0;
            const int a00 = ab0[w0];
            const int a01 = ab0[w0 ^ 4];
            const int a10 = ab1[w0 ^ 32];
            const int a11 = ab1[w0 ^ 36];
            const float ed0 = edst_sm[jc + kt * 8 + q];
            const float ed1 = edst_sm[jc + kt * 8 + q + 4];
            const float A0f = (a00 > 0) ? rna_tf32(fmaxf(es0 * ed0, 1.f)) : 0.f;
            const float A1f = (a10 > 0) ? rna_tf32(fmaxf(es1 * ed0, 1.f)) : 0.f;
            const float A2f = (a01 > 0) ? rna_tf32(fmaxf(es0 * ed1, 1.f)) : 0.f;
            const float A3f = (a11 > 0) ? rna_tf32(fmaxf(es1 * ed1, 1.f)) : 0.f;
            l0 += A0f + A2f;
            l1 += A1f + A3f;
            const uint A0 = __float_as_uint(A0f), A1 = __float_as_uint(A1f);
            const uint A2 = __float_as_uint(A2f), A3 = __float_as_uint(A3f);
            #pragma unroll
            for (int p = 0; p < 4; p++) {
                const float4 bq = *(const float4*)&hb[kt * 512 + hoff + p * 128];
                MMA_TF32(acc[2 * p],     A0, A1, A2, A3,
                         __float_as_uint(bq.x), __float_as_uint(bq.y));
                MMA_TF32(acc[2 * p + 1], A0, A1, A2, A3,
                         __float_as_uint(bq.z), __float_as_uint(bq.w));
            }
        }

        if (ck < 31) asm volatile("cp.async.wait_group 0;" ::: "memory");
        __syncthreads();
    }

    // l: each row's cols partition over the 4 q-lanes
    l0 += __shfl_xor_sync(0xffffffffu, l0, 1);
    l0 += __shfl_xor_sync(0xffffffffu, l0, 2);
    l1 += __shfl_xor_sync(0xffffffffu, l1, 1);
    l1 += __shfl_xor_sync(0xffffffffu, l1, 2);
    const float inv0 = 1.f / l0;
    const float inv1 = 1.f / l1;

    // epilogue: acc[2p+s] holds cols p*16 + s*8 + 2q (+1)
    const long rg = bn + ib + row0;
    #pragma unroll
    for (int nt = 0; nt < 8; nt++) {
        const int ncol = (nt >> 1) * 16 + (nt & 1) * 8 + 2 * q;
        *(float2*)(out + rg * 64 + ncol) =
            make_float2(acc[nt][0] * inv0, acc[nt][1] * inv0);
        *(float2*)(out + (rg + 8) * 64 + ncol) =
            make_float2(acc[nt][2] * inv1, acc[nt][3] * inv1);
    }
}

// ================================================================
// launch
// inputs: x f32[16,2048,256], adj i32[16,2048,2048],
//         weight f32[256,64], weight2 f32[128,1]
// output: f32[16,2048,64]
// ================================================================
extern "C" void kernel_launch(void* const* d_in, const int* in_sizes, int n_in,
                              void* d_out, int out_size) {
    const float* x   = (const float*)d_in[0];
    const int*   adj = (const int*)d_in[1];
    const float* W   = (const float*)d_in[2];
    const float* w2  = (const float*)d_in[3];
    float* out = (float*)d_out;

    cudaFuncSetAttribute(gemm_h_kernel,
                         cudaFuncAttributeMaxDynamicSharedMemorySize, 109312);
    cudaFuncSetAttribute(attn_kernel,
                         cudaFuncAttributeMaxDynamicSharedMemorySize, 106496);

    gemm_h_kernel<<<296, 256, 109312>>>(x, W, w2);         // persistent, 16-row tiles
    attn_kernel<<<dim3(16, 16), 256, 106496>>>(adj, out);  // 128 rows/CTA
}